// round 2
// baseline (speedup 1.0000x reference)
#include <cuda_runtime.h>
#include <cstdint>

#define NN 50000
#define NE 600000
#define DIM 128
#define KBIG 384
#define BN_EPS 1e-5f

// ---------------- scratch (static device globals; no allocation) -------------
__device__ float g_sums[NN * DIM];          // scatter accumulator
__device__ float g_cnt[NN];                 // edge counts per node
__device__ float g_comb[NN * KBIG];         // [x | v_e | u[batch]]
__device__ float g_h0[NN * DIM];            // layer-0 raw relu output
__device__ float g_h1[NN * DIM];            // layer-1 raw relu output
__device__ float g_stats[3 * 2 * DIM];      // per-stage {sum[128], sumsq[128]}
__device__ float g_Wf1[DIM * DIM];          // BN0-folded W1
__device__ float g_bf1[DIM];
__device__ float g_Wf2[DIM * DIM];          // BN1-folded W2
__device__ float g_bf2[DIM];
__device__ float g_a2c2[2 * DIM];           // final BN scale/shift
__device__ int   g_is64;                    // 1 if index tensors are int64

// ---------------- detect index dtype ----------------
// If the buffer is int64 (little-endian) holding small non-negative values,
// every odd 32-bit word (high half) is 0. If it is int32 holding random
// indices in [0, 50000), 1024 consecutive odd words can't all be zero.
__global__ void detect_kernel(const int* __restrict__ ei32) {
    __shared__ int any;
    int t = threadIdx.x;
    if (t == 0) any = 0;
    __syncthreads();
    for (int i = t; i < 1024; i += blockDim.x)
        if (ei32[2 * i + 1] != 0) atomicOr(&any, 1);
    __syncthreads();
    if (t == 0) g_is64 = (any == 0) ? 1 : 0;
}

__device__ __forceinline__ int load_idx(const void* p, int i) {
    if (g_is64) return (int)((const long long*)p)[i];
    return ((const int*)p)[i];
}

// ---------------- zero scratch ----------------
__global__ void zero_kernel() {
    int i = blockIdx.x * blockDim.x + threadIdx.x;
    int stride = gridDim.x * blockDim.x;
    float4 z = make_float4(0.f, 0.f, 0.f, 0.f);
    float4* s4 = reinterpret_cast<float4*>(g_sums);
    for (int j = i; j < NN * DIM / 4; j += stride) s4[j] = z;
    for (int j = i; j < NN; j += stride) g_cnt[j] = 0.f;
    for (int j = i; j < 3 * 2 * DIM; j += stride) g_stats[j] = 0.f;
}

// ---------------- scatter-add of edge features ----------------
// One warp per edge: 32 lanes x float4 = 128 floats.
__global__ void scatter_kernel(const void* __restrict__ ei,
                               const float* __restrict__ ea, int nE, int n) {
    int t = blockIdx.x * blockDim.x + threadIdx.x;
    int e = t >> 5;
    int lane = t & 31;
    if (e >= nE) return;
    int src = load_idx(ei, e);  // row 0 of edge_index
    if ((unsigned)src >= (unsigned)n) return;  // defensive
    float4 v = reinterpret_cast<const float4*>(ea)[(size_t)e * 32 + lane];
    float* dst = g_sums + (size_t)src * DIM + lane * 4;
    atomicAdd(dst + 0, v.x);
    atomicAdd(dst + 1, v.y);
    atomicAdd(dst + 2, v.z);
    atomicAdd(dst + 3, v.w);
    if (lane == 0) atomicAdd(&g_cnt[src], 1.f);
}

// ---------------- build comb = [x | sums/cnt | u[batch]] ----------------
__global__ void comb_kernel(const float* __restrict__ x,
                            const float* __restrict__ u,
                            const void* __restrict__ batch, int n, int nG) {
    int i = blockIdx.x * blockDim.x + threadIdx.x;
    int stride = gridDim.x * blockDim.x;
    const float4* x4 = reinterpret_cast<const float4*>(x);
    const float4* s4 = reinterpret_cast<const float4*>(g_sums);
    const float4* u4 = reinterpret_cast<const float4*>(u);
    float4* c4 = reinterpret_cast<float4*>(g_comb);
    for (int j = i; j < n * 32; j += stride) {
        int node = j >> 5;
        int q = j & 31;
        float inv = 1.f / fmaxf(g_cnt[node], 1.f);
        int b = load_idx(batch, node);
        if ((unsigned)b >= (unsigned)nG) b = 0;  // defensive
        float4 xv = x4[j];
        float4 sv = s4[j];
        sv.x *= inv; sv.y *= inv; sv.z *= inv; sv.w *= inv;
        float4 uv = u4[(size_t)b * 32 + q];
        c4[(size_t)node * 96 + q] = xv;
        c4[(size_t)node * 96 + 32 + q] = sv;
        c4[(size_t)node * 96 + 64 + q] = uv;
    }
}

// ---------------- fused GEMM + bias + relu + column-stats ----------------
// C[n,128] = relu(A[n,K] @ W[128,K]^T + bias); stats += {col sums, col sumsq}
template <int K>
__global__ void __launch_bounds__(256, 2)
gemm_kernel(const float* __restrict__ A, const float* __restrict__ W,
            const float* __restrict__ bias, float* __restrict__ C,
            float* __restrict__ stats, int n) {
    __shared__ float As[16][132];
    __shared__ float Bs[16][132];
    __shared__ float red[2][128];

    int tid = threadIdx.x;
    int tr = tid >> 4;   // 0..15 row group
    int tc = tid & 15;   // 0..15 col group
    int rowBase = blockIdx.x * 128;

    float acc[8][8];
#pragma unroll
    for (int i = 0; i < 8; i++)
#pragma unroll
        for (int j = 0; j < 8; j++) acc[i][j] = 0.f;

    for (int k0 = 0; k0 < K; k0 += 16) {
        // load A tile (128 rows x 16 k), transposed into k-major smem
#pragma unroll
        for (int l = 0; l < 2; l++) {
            int f = tid + l * 256;          // 0..511 float4 slots
            int row = f >> 2;
            int kq = (f & 3) * 4;
            float4 v = make_float4(0.f, 0.f, 0.f, 0.f);
            if (rowBase + row < n)
                v = *reinterpret_cast<const float4*>(
                    A + (size_t)(rowBase + row) * K + k0 + kq);
            As[kq + 0][row] = v.x;
            As[kq + 1][row] = v.y;
            As[kq + 2][row] = v.z;
            As[kq + 3][row] = v.w;
        }
        // load W tile (128 out-cols x 16 k), transposed
#pragma unroll
        for (int l = 0; l < 2; l++) {
            int f = tid + l * 256;
            int row = f >> 2;
            int kq = (f & 3) * 4;
            float4 v = *reinterpret_cast<const float4*>(
                W + (size_t)row * K + k0 + kq);
            Bs[kq + 0][row] = v.x;
            Bs[kq + 1][row] = v.y;
            Bs[kq + 2][row] = v.z;
            Bs[kq + 3][row] = v.w;
        }
        __syncthreads();
#pragma unroll
        for (int k = 0; k < 16; k++) {
            float4 a0 = *reinterpret_cast<float4*>(&As[k][tr * 8]);
            float4 a1 = *reinterpret_cast<float4*>(&As[k][tr * 8 + 4]);
            float4 b0 = *reinterpret_cast<float4*>(&Bs[k][tc * 8]);
            float4 b1 = *reinterpret_cast<float4*>(&Bs[k][tc * 8 + 4]);
            float av[8] = {a0.x, a0.y, a0.z, a0.w, a1.x, a1.y, a1.z, a1.w};
            float bv[8] = {b0.x, b0.y, b0.z, b0.w, b1.x, b1.y, b1.z, b1.w};
#pragma unroll
            for (int i = 0; i < 8; i++)
#pragma unroll
                for (int j = 0; j < 8; j++) acc[i][j] += av[i] * bv[j];
        }
        __syncthreads();
    }

    // epilogue: bias + relu + store + column stats
    float bb[8];
#pragma unroll
    for (int j = 0; j < 8; j++) bb[j] = __ldg(&bias[tc * 8 + j]);

    float s[8], q[8];
#pragma unroll
    for (int j = 0; j < 8; j++) { s[j] = 0.f; q[j] = 0.f; }

#pragma unroll
    for (int i = 0; i < 8; i++) {
        int row = rowBase + tr * 8 + i;
        if (row < n) {
#pragma unroll
            for (int j = 0; j < 8; j++) {
                float v = fmaxf(acc[i][j] + bb[j], 0.f);
                acc[i][j] = v;
                s[j] += v;
                q[j] += v * v;
            }
            float4 o0 = make_float4(acc[i][0], acc[i][1], acc[i][2], acc[i][3]);
            float4 o1 = make_float4(acc[i][4], acc[i][5], acc[i][6], acc[i][7]);
            *reinterpret_cast<float4*>(C + (size_t)row * 128 + tc * 8) = o0;
            *reinterpret_cast<float4*>(C + (size_t)row * 128 + tc * 8 + 4) = o1;
        }
    }

    if (tid < 128) { red[0][tid] = 0.f; red[1][tid] = 0.f; }
    __syncthreads();
#pragma unroll
    for (int j = 0; j < 8; j++) {
        atomicAdd(&red[0][tc * 8 + j], s[j]);
        atomicAdd(&red[1][tc * 8 + j], q[j]);
    }
    __syncthreads();
    if (tid < 128) {
        atomicAdd(&stats[tid], red[0][tid]);
        atomicAdd(&stats[128 + tid], red[1][tid]);
    }
}

// ---------------- fold BN(stage s) into next layer's weights ----------------
__global__ void fold_kernel(const float* __restrict__ stats,
                            const float* __restrict__ gamma,
                            const float* __restrict__ beta,
                            const float* __restrict__ Wn,
                            const float* __restrict__ bn,
                            float* __restrict__ Wf, float* __restrict__ bf,
                            float n) {
    __shared__ float a[128], c[128];
    int tid = threadIdx.x;  // 128 threads
    float m = stats[tid] / n;
    float var = stats[128 + tid] / n - m * m;
    float rs = rsqrtf(var + BN_EPS);
    a[tid] = gamma[tid] * rs;
    c[tid] = beta[tid] - gamma[tid] * m * rs;
    __syncthreads();
    float accb = 0.f;
#pragma unroll 4
    for (int k = 0; k < 128; k++) {
        float w = Wn[tid * 128 + k];
        Wf[tid * 128 + k] = w * a[k];
        accb += c[k] * w;
    }
    bf[tid] = bn[tid] + accb;
}

// ---------------- final BN scale/shift ----------------
__global__ void finalfold_kernel(const float* __restrict__ stats,
                                 const float* __restrict__ gamma,
                                 const float* __restrict__ beta, float n) {
    int tid = threadIdx.x;  // 128 threads
    float m = stats[tid] / n;
    float var = stats[128 + tid] / n - m * m;
    float rs = rsqrtf(var + BN_EPS);
    g_a2c2[tid] = gamma[tid] * rs;
    g_a2c2[128 + tid] = beta[tid] - gamma[tid] * m * rs;
}

// ---------------- apply final BN elementwise ----------------
__global__ void norm_kernel(float* __restrict__ out, int n) {
    int i = blockIdx.x * blockDim.x + threadIdx.x;
    int stride = gridDim.x * blockDim.x;
    float4* o4 = reinterpret_cast<float4*>(out);
    const float4* a4 = reinterpret_cast<const float4*>(g_a2c2);
    const float4* c4 = reinterpret_cast<const float4*>(g_a2c2 + 128);
    for (int j = i; j < n * 32; j += stride) {
        int q = j & 31;
        float4 v = o4[j];
        float4 a = a4[q];
        float4 c = c4[q];
        v.x = v.x * a.x + c.x;
        v.y = v.y * a.y + c.y;
        v.z = v.z * a.z + c.z;
        v.w = v.w * a.w + c.w;
        o4[j] = v;
    }
}

// ---------------- host launcher ----------------
extern "C" void kernel_launch(void* const* d_in, const int* in_sizes, int n_in,
                              void* d_out, int out_size) {
    const float* x = (const float*)d_in[0];
    const void* ei = d_in[1];
    const float* ea = (const float*)d_in[2];
    const float* u = (const float*)d_in[3];
    const void* batch = d_in[4];
    const float* W0 = (const float*)d_in[5];
    const float* b0 = (const float*)d_in[6];
    const float* W1 = (const float*)d_in[7];
    const float* b1 = (const float*)d_in[8];
    const float* W2 = (const float*)d_in[9];
    const float* b2 = (const float*)d_in[10];
    const float* g0 = (const float*)d_in[11];
    const float* be0 = (const float*)d_in[12];
    const float* g1 = (const float*)d_in[13];
    const float* be1 = (const float*)d_in[14];
    const float* g2 = (const float*)d_in[15];
    const float* be2 = (const float*)d_in[16];

    int n = in_sizes[0] / DIM;
    int nE = in_sizes[2] / DIM;
    int nG = in_sizes[3] / DIM;
    float* out = (float*)d_out;

    float *comb, *h0, *h1, *stats, *Wf1, *bf1, *Wf2, *bf2;
    cudaGetSymbolAddress((void**)&comb, g_comb);
    cudaGetSymbolAddress((void**)&h0, g_h0);
    cudaGetSymbolAddress((void**)&h1, g_h1);
    cudaGetSymbolAddress((void**)&stats, g_stats);
    cudaGetSymbolAddress((void**)&Wf1, g_Wf1);
    cudaGetSymbolAddress((void**)&bf1, g_bf1);
    cudaGetSymbolAddress((void**)&Wf2, g_Wf2);
    cudaGetSymbolAddress((void**)&bf2, g_bf2);

    detect_kernel<<<1, 256>>>((const int*)ei);
    zero_kernel<<<2048, 256>>>();
    scatter_kernel<<<(nE * 32 + 255) / 256, 256>>>(ei, ea, nE, n);
    comb_kernel<<<2048, 256>>>(x, u, batch, n, nG);

    int gblocks = (n + 127) / 128;
    gemm_kernel<KBIG><<<gblocks, 256>>>(comb, W0, b0, h0, stats, n);
    fold_kernel<<<1, 128>>>(stats, g0, be0, W1, b1, Wf1, bf1, (float)n);
    gemm_kernel<DIM><<<gblocks, 256>>>(h0, Wf1, bf1, h1, stats + 256, n);
    fold_kernel<<<1, 128>>>(stats + 256, g1, be1, W2, b2, Wf2, bf2, (float)n);
    gemm_kernel<DIM><<<gblocks, 256>>>(h1, Wf2, bf2, out, stats + 512, n);
    finalfold_kernel<<<1, 128>>>(stats + 512, g2, be2, (float)n);
    norm_kernel<<<1024, 256>>>(out, n);
}

// round 4
// speedup vs baseline: 2.4684x; 2.4684x over previous
#include <cuda_runtime.h>
#include <cuda_bf16.h>
#include <cstdint>

#define NN 50000
#define NE 600000
#define DIM 128
#define KBIG 384
#define BN_EPS 1e-5f

typedef __nv_bfloat16 bf16;

// ============================ scratch globals ================================
__device__ float g_sums[NN * DIM];
__device__ float g_cnt[NN];
__device__ bf16 g_combh[NN * KBIG];
__device__ bf16 g_combl[NN * KBIG];
__device__ bf16 g_h0h[NN * DIM];
__device__ bf16 g_h0l[NN * DIM];
__device__ bf16 g_h1h[NN * DIM];
__device__ bf16 g_h1l[NN * DIM];
__device__ bf16 g_w0h[DIM * KBIG];
__device__ bf16 g_w0l[DIM * KBIG];
__device__ bf16 g_wf1h[DIM * DIM];
__device__ bf16 g_wf1l[DIM * DIM];
__device__ bf16 g_wf2h[DIM * DIM];
__device__ bf16 g_wf2l[DIM * DIM];
__device__ float g_bf1[DIM];
__device__ float g_bf2[DIM];
__device__ float g_stats[3 * 2 * DIM];
__device__ float g_a2c2[2 * DIM];
__device__ int g_is64;

__device__ __forceinline__ uint32_t pack2bf(float a, float b) {
    __nv_bfloat162 t = __floats2bfloat162_rn(a, b);
    return *reinterpret_cast<uint32_t*>(&t);
}

// ============================ small kernels ==================================
__global__ void detect_kernel(const int* __restrict__ ei32) {
    __shared__ int any;
    int t = threadIdx.x;
    if (t == 0) any = 0;
    __syncthreads();
    for (int i = t; i < 1024; i += blockDim.x)
        if (ei32[2 * i + 1] != 0) atomicOr(&any, 1);
    __syncthreads();
    if (t == 0) g_is64 = (any == 0) ? 1 : 0;
}

__device__ __forceinline__ int load_idx(const void* p, int i) {
    if (g_is64) return (int)((const long long*)p)[i];
    return ((const int*)p)[i];
}

__global__ void zero_kernel() {
    int i = blockIdx.x * blockDim.x + threadIdx.x;
    int stride = gridDim.x * blockDim.x;
    float4 z = make_float4(0.f, 0.f, 0.f, 0.f);
    float4* s4 = reinterpret_cast<float4*>(g_sums);
    for (int j = i; j < NN * DIM / 4; j += stride) s4[j] = z;
    for (int j = i; j < NN; j += stride) g_cnt[j] = 0.f;
    for (int j = i; j < 3 * 2 * DIM; j += stride) g_stats[j] = 0.f;
}

__global__ void scatter_kernel(const void* __restrict__ ei,
                               const float* __restrict__ ea, int nE, int n) {
    int t = blockIdx.x * blockDim.x + threadIdx.x;
    int e = t >> 5;
    int lane = t & 31;
    if (e >= nE) return;
    int src = load_idx(ei, e);
    if ((unsigned)src >= (unsigned)n) return;
    float4 v = reinterpret_cast<const float4*>(ea)[(size_t)e * 32 + lane];
    float* dst = g_sums + (size_t)src * DIM + lane * 4;
    asm volatile("red.global.add.v4.f32 [%0], {%1, %2, %3, %4};"
                 :: "l"(dst), "f"(v.x), "f"(v.y), "f"(v.z), "f"(v.w)
                 : "memory");
    if (lane == 0) atomicAdd(&g_cnt[src], 1.f);
}

__device__ __forceinline__ void split4(float4 v, uint2& H, uint2& L) {
    bf16 h0 = __float2bfloat16_rn(v.x);
    bf16 h1 = __float2bfloat16_rn(v.y);
    bf16 h2 = __float2bfloat16_rn(v.z);
    bf16 h3 = __float2bfloat16_rn(v.w);
    float l0 = v.x - __bfloat162float(h0);
    float l1 = v.y - __bfloat162float(h1);
    float l2 = v.z - __bfloat162float(h2);
    float l3 = v.w - __bfloat162float(h3);
    __nv_bfloat162 p01; p01.x = h0; p01.y = h1;
    __nv_bfloat162 p23; p23.x = h2; p23.y = h3;
    H.x = *reinterpret_cast<uint32_t*>(&p01);
    H.y = *reinterpret_cast<uint32_t*>(&p23);
    L.x = pack2bf(l0, l1);
    L.y = pack2bf(l2, l3);
}

__global__ void comb_kernel(const float* __restrict__ x,
                            const float* __restrict__ u,
                            const void* __restrict__ batch, int n, int nG) {
    int i = blockIdx.x * blockDim.x + threadIdx.x;
    int stride = gridDim.x * blockDim.x;
    const float4* x4 = reinterpret_cast<const float4*>(x);
    const float4* s4 = reinterpret_cast<const float4*>(g_sums);
    const float4* u4 = reinterpret_cast<const float4*>(u);
    uint2* ch = reinterpret_cast<uint2*>(g_combh);
    uint2* cl = reinterpret_cast<uint2*>(g_combl);
    for (int j = i; j < n * 32; j += stride) {
        int node = j >> 5;
        int q = j & 31;
        float inv = 1.f / fmaxf(g_cnt[node], 1.f);
        int b = load_idx(batch, node);
        if ((unsigned)b >= (unsigned)nG) b = 0;
        float4 xv = x4[j];
        float4 sv = s4[j];
        sv.x *= inv; sv.y *= inv; sv.z *= inv; sv.w *= inv;
        float4 uv = u4[(size_t)b * 32 + q];
        uint2 H, L;
        size_t base = (size_t)node * 96;
        split4(xv, H, L); ch[base + q] = H;      cl[base + q] = L;
        split4(sv, H, L); ch[base + 32 + q] = H; cl[base + 32 + q] = L;
        split4(uv, H, L); ch[base + 64 + q] = H; cl[base + 64 + q] = L;
    }
}

__global__ void w0split_kernel(const float* __restrict__ W0) {
    int i = blockIdx.x * blockDim.x + threadIdx.x;
    if (i >= DIM * KBIG) return;
    float w = W0[i];
    bf16 h = __float2bfloat16_rn(w);
    g_w0h[i] = h;
    g_w0l[i] = __float2bfloat16_rn(w - __bfloat162float(h));
}

__global__ void fold_kernel(const float* __restrict__ stats,
                            const float* __restrict__ gamma,
                            const float* __restrict__ beta,
                            const float* __restrict__ Wn,
                            const float* __restrict__ bn,
                            bf16* __restrict__ Wh, bf16* __restrict__ Wl,
                            float* __restrict__ bf, float n) {
    __shared__ float a[128], c[128];
    int tid = threadIdx.x;
    float m = stats[tid] / n;
    float var = stats[128 + tid] / n - m * m;
    float rs = rsqrtf(var + BN_EPS);
    a[tid] = gamma[tid] * rs;
    c[tid] = beta[tid] - gamma[tid] * m * rs;
    __syncthreads();
    float accb = 0.f;
#pragma unroll 4
    for (int k = 0; k < 128; k++) {
        float w = Wn[tid * 128 + k];
        float wf = w * a[k];
        bf16 h = __float2bfloat16_rn(wf);
        Wh[tid * 128 + k] = h;
        Wl[tid * 128 + k] = __float2bfloat16_rn(wf - __bfloat162float(h));
        accb += c[k] * w;
    }
    bf[tid] = bn[tid] + accb;
}

__global__ void finalfold_kernel(const float* __restrict__ stats,
                                 const float* __restrict__ gamma,
                                 const float* __restrict__ beta, float n) {
    int tid = threadIdx.x;
    float m = stats[tid] / n;
    float var = stats[128 + tid] / n - m * m;
    float rs = rsqrtf(var + BN_EPS);
    g_a2c2[tid] = gamma[tid] * rs;
    g_a2c2[128 + tid] = beta[tid] - gamma[tid] * m * rs;
}

__global__ void norm_kernel(float* __restrict__ out, int n) {
    int i = blockIdx.x * blockDim.x + threadIdx.x;
    int stride = gridDim.x * blockDim.x;
    float4* o4 = reinterpret_cast<float4*>(out);
    const float4* a4 = reinterpret_cast<const float4*>(g_a2c2);
    const float4* c4 = reinterpret_cast<const float4*>(g_a2c2 + 128);
    for (int j = i; j < n * 32; j += stride) {
        int q = j & 31;
        float4 v = o4[j];
        float4 a = a4[q];
        float4 c = c4[q];
        v.x = v.x * a.x + c.x;
        v.y = v.y * a.y + c.y;
        v.z = v.z * a.z + c.z;
        v.w = v.w * a.w + c.w;
        o4[j] = v;
    }
}

// ====================== mma.sync bf16-split GEMM =============================
__device__ __forceinline__ void mma16816(float* c, const uint32_t* a,
                                         uint32_t b0, uint32_t b1) {
    asm volatile(
        "mma.sync.aligned.m16n8k16.row.col.f32.bf16.bf16.f32 "
        "{%0,%1,%2,%3}, {%4,%5,%6,%7}, {%8,%9}, {%0,%1,%2,%3};"
        : "+f"(c[0]), "+f"(c[1]), "+f"(c[2]), "+f"(c[3])
        : "r"(a[0]), "r"(a[1]), "r"(a[2]), "r"(a[3]), "r"(b0), "r"(b1));
}

static constexpr int LDSTR = 72;  // padded smem row stride (bf16 elems)
static constexpr int TILE_ELEMS = 128 * LDSTR;
static constexpr int GEMM_SMEM = 4 * TILE_ELEMS * 2 + 3 * 128 * 4;

template <int K, bool LAST>
__global__ void __launch_bounds__(256)
gemm_mma(const bf16* __restrict__ Ah, const bf16* __restrict__ Al,
         const bf16* __restrict__ Wh, const bf16* __restrict__ Wl,
         const float* __restrict__ bias, float* __restrict__ outF,
         bf16* __restrict__ Ch, bf16* __restrict__ Cl,
         float* __restrict__ stats, int n) {
    extern __shared__ __align__(16) char dsm[];
    bf16* sAh = reinterpret_cast<bf16*>(dsm);
    bf16* sAl = sAh + TILE_ELEMS;
    bf16* sWh = sAl + TILE_ELEMS;
    bf16* sWl = sWh + TILE_ELEMS;
    float* red0 = reinterpret_cast<float*>(dsm + 4 * TILE_ELEMS * 2);
    float* red1 = red0 + 128;
    float* sbias = red1 + 128;

    const int tid = threadIdx.x;
    const int wid = tid >> 5;
    const int lane = tid & 31;
    const int warp_m = wid & 3;   // 0..3 (32 rows each)
    const int warp_n = wid >> 2;  // 0..1 (64 cols each)
    const int groupID = lane >> 2;
    const int tig = lane & 3;
    const int rowBase = blockIdx.x * 128;

    if (tid < 128) {
        red0[tid] = 0.f;
        red1[tid] = 0.f;
        sbias[tid] = bias[tid];
    }

    float acc[2][8][4];
#pragma unroll
    for (int mt = 0; mt < 2; mt++)
#pragma unroll
        for (int nt = 0; nt < 8; nt++)
#pragma unroll
            for (int q = 0; q < 4; q++) acc[mt][nt][q] = 0.f;

    const int lrow = tid >> 1;
    const int lhalf = (tid & 1) * 32;
    const bool rowOK = (rowBase + lrow) < n;

#pragma unroll 1
    for (int c = 0; c < K / 64; c++) {
        const int k0 = c * 64;
        if (c > 0) __syncthreads();
        // global -> smem (each thread: 4 uint4 per tile)
        {
            const uint4* pAh = reinterpret_cast<const uint4*>(
                Ah + (size_t)(rowBase + lrow) * K + k0 + lhalf);
            const uint4* pAl = reinterpret_cast<const uint4*>(
                Al + (size_t)(rowBase + lrow) * K + k0 + lhalf);
            const uint4* pWh = reinterpret_cast<const uint4*>(
                Wh + (size_t)lrow * K + k0 + lhalf);
            const uint4* pWl = reinterpret_cast<const uint4*>(
                Wl + (size_t)lrow * K + k0 + lhalf);
            uint4 z = make_uint4(0, 0, 0, 0);
#pragma unroll
            for (int i = 0; i < 4; i++) {
                uint4 vh = rowOK ? pAh[i] : z;
                uint4 vl = rowOK ? pAl[i] : z;
                uint4 wh = pWh[i];
                uint4 wl = pWl[i];
                int off = lrow * LDSTR + lhalf + i * 8;
                *reinterpret_cast<uint4*>(sAh + off) = vh;
                *reinterpret_cast<uint4*>(sAl + off) = vl;
                *reinterpret_cast<uint4*>(sWh + off) = wh;
                *reinterpret_cast<uint4*>(sWl + off) = wl;
            }
        }
        __syncthreads();

#pragma unroll
        for (int kk = 0; kk < 4; kk++) {
            const int ac = kk * 16 + tig * 2;
            uint32_t aH[2][4], aL[2][4];
#pragma unroll
            for (int mt = 0; mt < 2; mt++) {
                int r = warp_m * 32 + mt * 16 + groupID;
                const bf16* pH = sAh + r * LDSTR + ac;
                const bf16* pL = sAl + r * LDSTR + ac;
                aH[mt][0] = *reinterpret_cast<const uint32_t*>(pH);
                aH[mt][1] = *reinterpret_cast<const uint32_t*>(pH + 8 * LDSTR);
                aH[mt][2] = *reinterpret_cast<const uint32_t*>(pH + 8);
                aH[mt][3] = *reinterpret_cast<const uint32_t*>(pH + 8 * LDSTR + 8);
                aL[mt][0] = *reinterpret_cast<const uint32_t*>(pL);
                aL[mt][1] = *reinterpret_cast<const uint32_t*>(pL + 8 * LDSTR);
                aL[mt][2] = *reinterpret_cast<const uint32_t*>(pL + 8);
                aL[mt][3] = *reinterpret_cast<const uint32_t*>(pL + 8 * LDSTR + 8);
            }
#pragma unroll
            for (int nt = 0; nt < 8; nt++) {
                int wr = warp_n * 64 + nt * 8 + groupID;
                const bf16* qH = sWh + wr * LDSTR + ac;
                const bf16* qL = sWl + wr * LDSTR + ac;
                uint32_t bH0 = *reinterpret_cast<const uint32_t*>(qH);
                uint32_t bH1 = *reinterpret_cast<const uint32_t*>(qH + 8);
                uint32_t bL0 = *reinterpret_cast<const uint32_t*>(qL);
                uint32_t bL1 = *reinterpret_cast<const uint32_t*>(qL + 8);
#pragma unroll
                for (int mt = 0; mt < 2; mt++) {
                    mma16816(acc[mt][nt], aH[mt], bH0, bH1);
                    mma16816(acc[mt][nt], aL[mt], bH0, bH1);
                    mma16816(acc[mt][nt], aH[mt], bL0, bL1);
                }
            }
        }
    }

    // ---------------- epilogue: bias + relu + stats + store ----------------
#pragma unroll
    for (int mt = 0; mt < 2; mt++) {
        int r0 = rowBase + warp_m * 32 + mt * 16 + groupID;
        int r1 = r0 + 8;
#pragma unroll
        for (int nt = 0; nt < 8; nt++) {
            int j = warp_n * 64 + nt * 8 + tig * 2;
            float* a = acc[mt][nt];
            float b0v = sbias[j], b1v = sbias[j + 1];
            float v0 = (r0 < n) ? fmaxf(a[0] + b0v, 0.f) : 0.f;
            float v1 = (r0 < n) ? fmaxf(a[1] + b1v, 0.f) : 0.f;
            float v2 = (r1 < n) ? fmaxf(a[2] + b0v, 0.f) : 0.f;
            float v3 = (r1 < n) ? fmaxf(a[3] + b1v, 0.f) : 0.f;

            float s0 = v0 + v2, s1 = v1 + v3;
            float q0 = v0 * v0 + v2 * v2, q1 = v1 * v1 + v3 * v3;
#pragma unroll
            for (int off = 4; off < 32; off <<= 1) {
                s0 += __shfl_xor_sync(0xffffffffu, s0, off);
                s1 += __shfl_xor_sync(0xffffffffu, s1, off);
                q0 += __shfl_xor_sync(0xffffffffu, q0, off);
                q1 += __shfl_xor_sync(0xffffffffu, q1, off);
            }
            if (groupID == 0) {
                atomicAdd(red0 + j, s0);
                atomicAdd(red0 + j + 1, s1);
                atomicAdd(red1 + j, q0);
                atomicAdd(red1 + j + 1, q1);
            }

            if (LAST) {
                if (r0 < n)
                    *reinterpret_cast<float2*>(outF + (size_t)r0 * 128 + j) =
                        make_float2(v0, v1);
                if (r1 < n)
                    *reinterpret_cast<float2*>(outF + (size_t)r1 * 128 + j) =
                        make_float2(v2, v3);
            } else {
                if (r0 < n) {
                    bf16 h0 = __float2bfloat16_rn(v0);
                    bf16 h1 = __float2bfloat16_rn(v1);
                    __nv_bfloat162 hp; hp.x = h0; hp.y = h1;
                    *reinterpret_cast<uint32_t*>(Ch + (size_t)r0 * 128 + j) =
                        *reinterpret_cast<uint32_t*>(&hp);
                    *reinterpret_cast<uint32_t*>(Cl + (size_t)r0 * 128 + j) =
                        pack2bf(v0 - __bfloat162float(h0), v1 - __bfloat162float(h1));
                }
                if (r1 < n) {
                    bf16 h2 = __float2bfloat16_rn(v2);
                    bf16 h3 = __float2bfloat16_rn(v3);
                    __nv_bfloat162 hp; hp.x = h2; hp.y = h3;
                    *reinterpret_cast<uint32_t*>(Ch + (size_t)r1 * 128 + j) =
                        *reinterpret_cast<uint32_t*>(&hp);
                    *reinterpret_cast<uint32_t*>(Cl + (size_t)r1 * 128 + j) =
                        pack2bf(v2 - __bfloat162float(h2), v3 - __bfloat162float(h3));
                }
            }
        }
    }
    __syncthreads();
    if (tid < 128) {
        atomicAdd(&stats[tid], red0[tid]);
        atomicAdd(&stats[128 + tid], red1[tid]);
    }
}

// ============================ host launcher ==================================
extern "C" void kernel_launch(void* const* d_in, const int* in_sizes, int n_in,
                              void* d_out, int out_size) {
    const float* x = (const float*)d_in[0];
    const void* ei = d_in[1];
    const float* ea = (const float*)d_in[2];
    const float* u = (const float*)d_in[3];
    const void* batch = d_in[4];
    const float* W0 = (const float*)d_in[5];
    const float* b0 = (const float*)d_in[6];
    const float* W1 = (const float*)d_in[7];
    const float* b1 = (const float*)d_in[8];
    const float* W2 = (const float*)d_in[9];
    const float* b2 = (const float*)d_in[10];
    const float* g0 = (const float*)d_in[11];
    const float* be0 = (const float*)d_in[12];
    const float* g1 = (const float*)d_in[13];
    const float* be1 = (const float*)d_in[14];
    const float* g2 = (const float*)d_in[15];
    const float* be2 = (const float*)d_in[16];

    int n = in_sizes[0] / DIM;
    int nE = in_sizes[2] / DIM;
    int nG = in_sizes[3] / DIM;
    float* out = (float*)d_out;

    bf16 *combh, *combl, *h0h, *h0l, *h1h, *h1l;
    bf16 *w0h, *w0l, *wf1h, *wf1l, *wf2h, *wf2l;
    float *stats, *bf1, *bf2;
    cudaGetSymbolAddress((void**)&combh, g_combh);
    cudaGetSymbolAddress((void**)&combl, g_combl);
    cudaGetSymbolAddress((void**)&h0h, g_h0h);
    cudaGetSymbolAddress((void**)&h0l, g_h0l);
    cudaGetSymbolAddress((void**)&h1h, g_h1h);
    cudaGetSymbolAddress((void**)&h1l, g_h1l);
    cudaGetSymbolAddress((void**)&w0h, g_w0h);
    cudaGetSymbolAddress((void**)&w0l, g_w0l);
    cudaGetSymbolAddress((void**)&wf1h, g_wf1h);
    cudaGetSymbolAddress((void**)&wf1l, g_wf1l);
    cudaGetSymbolAddress((void**)&wf2h, g_wf2h);
    cudaGetSymbolAddress((void**)&wf2l, g_wf2l);
    cudaGetSymbolAddress((void**)&stats, g_stats);
    cudaGetSymbolAddress((void**)&bf1, g_bf1);
    cudaGetSymbolAddress((void**)&bf2, g_bf2);

    cudaFuncSetAttribute(gemm_mma<KBIG, false>,
                         cudaFuncAttributeMaxDynamicSharedMemorySize, GEMM_SMEM);
    cudaFuncSetAttribute(gemm_mma<DIM, false>,
                         cudaFuncAttributeMaxDynamicSharedMemorySize, GEMM_SMEM);
    cudaFuncSetAttribute(gemm_mma<DIM, true>,
                         cudaFuncAttributeMaxDynamicSharedMemorySize, GEMM_SMEM);

    detect_kernel<<<1, 256>>>((const int*)ei);
    zero_kernel<<<2048, 256>>>();
    scatter_kernel<<<(nE * 32 + 255) / 256, 256>>>(ei, ea, nE, n);
    comb_kernel<<<2048, 256>>>(x, u, batch, n, nG);
    w0split_kernel<<<(DIM * KBIG + 255) / 256, 256>>>(W0);

    int gblocks = (n + 127) / 128;
    gemm_mma<KBIG, false><<<gblocks, 256, GEMM_SMEM>>>(
        combh, combl, w0h, w0l, b0, nullptr, h0h, h0l, stats, n);
    fold_kernel<<<1, 128>>>(stats, g0, be0, W1, b1, wf1h, wf1l, bf1, (float)n);
    gemm_mma<DIM, false><<<gblocks, 256, GEMM_SMEM>>>(
        h0h, h0l, wf1h, wf1l, bf1, nullptr, h1h, h1l, stats + 256, n);
    fold_kernel<<<1, 128>>>(stats + 256, g1, be1, W2, b2, wf2h, wf2l, bf2, (float)n);
    gemm_mma<DIM, true><<<gblocks, 256, GEMM_SMEM>>>(
        h1h, h1l, wf2h, wf2l, bf2, out, nullptr, nullptr, stats + 512, n);
    finalfold_kernel<<<1, 128>>>(stats + 512, g2, be2, (float)n);
    norm_kernel<<<1024, 256>>>(out, n);
}